// round 14
// baseline (speedup 1.0000x reference)
#include <cuda_runtime.h>
#include <cuda_bf16.h>
#include <math.h>

#define Dn   128
#define SQn  16
#define SKn  4096
#define BHn  64
#define TILE 128
#define NTHREADS 256
#define NWARPS   8
#define NBLOCKS  (BHn * (SKn / TILE))   /* 2048 */
#define PADB 136                         /* padded bf16 row stride (ushorts) */

#define TAU_Y 1e-5f
#define TAU_P 1e-4f

typedef unsigned long long u64;
typedef unsigned int u32;
typedef unsigned short u16;

/* device scratch (no allocation allowed) */
__device__ float g_Rt[Dn*Dn];
__device__ float g_St[Dn*Dn];
__device__ float g_qR[BHn*SQn*Dn];
__device__ float g_qS[BHn*SQn*Dn];
/* bf16-split padded row-major images: [hi/lo][j*PADB + d] */
__device__ __align__(16) u16 g_BR16[2][Dn*PADB];
__device__ __align__(16) u16 g_BS16[2][Dn*PADB];

/* ---- prep 1: transposes + bf16-split images ---- */
__global__ void prep1(const float* __restrict__ rot, const float* __restrict__ S)
{
    int j = blockIdx.x, d = threadIdx.x;       /* 128 x 128 */
    float vR = rot[j*Dn + d];
    float vS = S[j*Dn + d];
    g_Rt[d*Dn + j] = vR;
    g_St[d*Dn + j] = vS;

    __nv_bfloat16 hR = __float2bfloat16_rn(vR);
    __nv_bfloat16 lR = __float2bfloat16_rn(vR - __bfloat162float(hR));
    g_BR16[0][j*PADB + d] = __bfloat16_as_ushort(hR);
    g_BR16[1][j*PADB + d] = __bfloat16_as_ushort(lR);
    __nv_bfloat16 hS = __float2bfloat16_rn(vS);
    __nv_bfloat16 lS = __float2bfloat16_rn(vS - __bfloat162float(hS));
    g_BS16[0][j*PADB + d] = __bfloat16_as_ushort(hS);
    g_BS16[1][j*PADB + d] = __bfloat16_as_ushort(lS);
}

/* ---- prep 2 (coalesced): qR/qS, continuous outputs ---- */
__global__ void prep_q(const float* __restrict__ query)
{
    __shared__ float sq[Dn];
    const int bq = blockIdx.x;
    const int j  = threadIdx.x;
    if (j < Dn) sq[j] = query[(size_t)bq*Dn + j];
    __syncthreads();

    float a0=0.f,a1=0.f,a2=0.f,a3=0.f, b0=0.f,b1=0.f,b2=0.f,b3=0.f;
#pragma unroll 8
    for (int d = 0; d < Dn; d += 4) {
        float q0 = sq[d+0], q1 = sq[d+1], q2 = sq[d+2], q3 = sq[d+3];
        a0 = __fmaf_rn(q0, g_Rt[(d+0)*Dn + j], a0);
        a1 = __fmaf_rn(q1, g_Rt[(d+1)*Dn + j], a1);
        a2 = __fmaf_rn(q2, g_Rt[(d+2)*Dn + j], a2);
        a3 = __fmaf_rn(q3, g_Rt[(d+3)*Dn + j], a3);
        b0 = __fmaf_rn(q0, g_St[(d+0)*Dn + j], b0);
        b1 = __fmaf_rn(q1, g_St[(d+1)*Dn + j], b1);
        b2 = __fmaf_rn(q2, g_St[(d+2)*Dn + j], b2);
        b3 = __fmaf_rn(q3, g_St[(d+3)*Dn + j], b3);
    }
    g_qR[(size_t)bq*Dn + j] = (a0 + a1) + (a2 + a3);
    g_qS[(size_t)bq*Dn + j] = (b0 + b1) + (b2 + b3);
}

__device__ __forceinline__ float wsum(float v)
{
#pragma unroll
    for (int o = 16; o > 0; o >>= 1) v += __shfl_xor_sync(0xffffffffu, v, o);
    return v;
}

/* ---- packed f32x2 helpers (phase 2) ---- */
__device__ __forceinline__ u64 pk2(float lo, float hi)
{ u64 r; asm("mov.b64 %0,{%1,%2};" : "=l"(r) : "f"(lo), "f"(hi)); return r; }
__device__ __forceinline__ u64 dup2(float x)
{ u64 r; asm("mov.b64 %0,{%1,%1};" : "=l"(r) : "f"(x)); return r; }
__device__ __forceinline__ void fma2(u64& acc, u64 a, u64 b)
{ asm("fma.rn.f32x2 %0,%1,%2,%0;" : "+l"(acc) : "l"(a), "l"(b)); }
__device__ __forceinline__ float2 unpk(u64 v)
{ float2 f; asm("mov.b64 {%0,%1},%2;" : "=f"(f.x), "=f"(f.y) : "l"(v)); return f; }

/* ---- warp MMA m16n8k16 bf16 (baseline sm_80 PTX, works on sm_103) ---- */
__device__ __forceinline__ void mma16816(float& c0, float& c1, float& c2, float& c3,
                                         u32 a0, u32 a1, u32 a2, u32 a3, u32 b0, u32 b1)
{
    asm volatile("mma.sync.aligned.m16n8k16.row.col.f32.bf16.bf16.f32 "
        "{%0,%1,%2,%3},{%4,%5,%6,%7},{%8,%9},{%0,%1,%2,%3};"
        : "+f"(c0), "+f"(c1), "+f"(c2), "+f"(c3)
        : "r"(a0), "r"(a1), "r"(a2), "r"(a3), "r"(b0), "r"(b1));
}

/* split a float2 into packed bf16 hi / lo words */
__device__ __forceinline__ void cvt_split(float2 v, u32& h, u32& l)
{
    __nv_bfloat16 h0 = __float2bfloat16_rn(v.x), h1 = __float2bfloat16_rn(v.y);
    float r0 = v.x - __bfloat162float(h0), r1 = v.y - __bfloat162float(h1);
    __nv_bfloat16 l0 = __float2bfloat16_rn(r0), l1 = __float2bfloat16_rn(r1);
    h = (u32)__bfloat16_as_ushort(h0) | ((u32)__bfloat16_as_ushort(h1) << 16);
    l = (u32)__bfloat16_as_ushort(l0) | ((u32)__bfloat16_as_ushort(l1) << 16);
}

/* ---- main fused kernel ---- */
__global__ void __launch_bounds__(NTHREADS, 1)
turbo_main(const float* __restrict__ keys, const float* __restrict__ rot,
           const float* __restrict__ Sm, const float* __restrict__ levels,
           float* __restrict__ out)
{
    __shared__ __align__(16) unsigned char uM[2*Dn*PADB*2]; /* 69632: bf16 imgs / fp32 rot */
    __shared__ float  sK[TILE*Dn];      /* 64K: keys -> k_hat -> y -> r_hat */
    __shared__ float  sQR[SQn*Dn];
    __shared__ float  sQS[SQn*Dn];
    __shared__ float  sTab[256*4];
    __shared__ float  sNorm[TILE];
    __shared__ float  sRn[TILE];
    __shared__ unsigned sSign[TILE*4];
    __shared__ unsigned char sCodeB[TILE*32];

    const int tid = threadIdx.x, w = tid >> 5, lane = tid & 31;
    const int gid = lane >> 2, tig = lane & 3;
    const int bh  = blockIdx.x >> 5;
    const int k0  = (blockIdx.x & 31) * TILE;
    const float* keys_blk = keys + ((size_t)bh*SKn + k0)*Dn;

    const float L0 = __ldg(levels+0), L1 = __ldg(levels+1),
                L2 = __ldg(levels+2), L3 = __ldg(levels+3);
    const float bb0 = 0.5f*(L0+L1), bb1 = 0.5f*(L1+L2), bb2 = 0.5f*(L2+L3);

    /* cooperative loads: keys, R bf16 images, qR/qS, level table */
    {
        const float4* g = (const float4*)keys_blk;
        float4* s = (float4*)sK;
#pragma unroll
        for (int i = tid; i < TILE*Dn/4; i += NTHREADS) s[i] = g[i];
    }
    {
        const float4* g = (const float4*)g_BR16; float4* s = (float4*)uM;
#pragma unroll
        for (int i = tid; i < (2*Dn*PADB*2)/16; i += NTHREADS) s[i] = g[i];
    }
    {
        const float4* g = (const float4*)(g_qR + bh*SQn*Dn); float4* s = (float4*)sQR;
#pragma unroll
        for (int i = tid; i < SQn*Dn/4; i += NTHREADS) s[i] = g[i];
        g = (const float4*)(g_qS + bh*SQn*Dn); s = (float4*)sQS;
#pragma unroll
        for (int i = tid; i < SQn*Dn/4; i += NTHREADS) s[i] = g[i];
    }
    {
        unsigned b = tid;
        float v[4];
#pragma unroll
        for (int c = 0; c < 4; ++c) {
            unsigned cc = (b >> (2*c)) & 3u;
            float lo = (cc & 1u) ? L1 : L0;
            float hi = (cc & 1u) ? L3 : L2;
            v[c] = (cc & 2u) ? hi : lo;
        }
        ((float4*)sTab)[b] = make_float4(v[0],v[1],v[2],v[3]);
    }
    __syncthreads();

    const int kb = w*16;

    /* norms (fp32, deterministic order, R12 chain) */
#pragma unroll
    for (int i = 0; i < 16; ++i) {
        int key = kb + i;
        float4 v = ((const float4*)(sK + key*Dn))[lane];
        float ss = __fmul_rn(v.x, v.x);
        ss = __fmaf_rn(v.y, v.y, ss);
        ss = __fmaf_rn(v.z, v.z, ss);
        ss = __fmaf_rn(v.w, v.w, ss);
        ss = wsum(ss);
        if (lane == 0) sNorm[key] = fmaxf(__fsqrt_rn(ss), 1e-8f);
    }
    __syncthreads();

    /* k_hat = fl(k / n) in place (IEEE div, R12 chain) */
#pragma unroll
    for (int i = tid; i < TILE*Dn; i += NTHREADS)
        sK[i] = __fdiv_rn(sK[i], sNorm[i >> 7]);
    __syncthreads();

    /* ===== phase 1 (TENSOR): Y = split(k_hat) @ split(R)^T, tau-filtered ===== */
    {
        const u16* Bh = (const u16*)uM;
        const u16* Bl = Bh + Dn*PADB;
        const float* rowA = sK + (kb + gid)*Dn;
        const float* rowB = sK + (kb + 8 + gid)*Dn;
        u32 AH[8][4], AL[8][4];
#pragma unroll
        for (int kc = 0; kc < 8; ++kc) {
            int d0 = 16*kc + 2*tig;
            cvt_split(*(const float2*)(rowA + d0),     AH[kc][0], AL[kc][0]);
            cvt_split(*(const float2*)(rowB + d0),     AH[kc][1], AL[kc][1]);
            cvt_split(*(const float2*)(rowA + d0 + 8), AH[kc][2], AL[kc][2]);
            cvt_split(*(const float2*)(rowB + d0 + 8), AH[kc][3], AL[kc][3]);
        }
        __syncwarp();
#pragma unroll 4
        for (int nt = 0; nt < 16; ++nt) {
            float c0 = 0.f, c1 = 0.f, c2 = 0.f, c3 = 0.f;
            const u16* bh = Bh + (8*nt + gid)*PADB + 2*tig;
            const u16* bl = Bl + (8*nt + gid)*PADB + 2*tig;
#pragma unroll
            for (int kc = 0; kc < 8; ++kc) {
                u32 b0 = *(const u32*)(bh + 16*kc);
                u32 b1 = *(const u32*)(bh + 16*kc + 8);
                u32 d0 = *(const u32*)(bl + 16*kc);
                u32 d1 = *(const u32*)(bl + 16*kc + 8);
                mma16816(c0,c1,c2,c3, AH[kc][0],AH[kc][1],AH[kc][2],AH[kc][3], b0,b1);
                mma16816(c0,c1,c2,c3, AL[kc][0],AL[kc][1],AL[kc][2],AL[kc][3], b0,b1);
                mma16816(c0,c1,c2,c3, AH[kc][0],AH[kc][1],AH[kc][2],AH[kc][3], d0,d1);
            }
            float* w0 = sK + (kb + gid)*Dn     + 8*nt + 2*tig;
            float* w1 = sK + (kb + 8 + gid)*Dn + 8*nt + 2*tig;
            w0[0] = c0; w0[1] = c1; w1[0] = c2; w1[1] = c3;
        }
        __syncwarp();
        /* quantize from staged y, tau-filter with exact R12 fp32-chain recompute */
#pragma unroll
        for (int i = 0; i < 16; ++i) {
            int key = kb + i;
            float4 y4 = ((const float4*)(sK + key*Dn))[lane];
            float ys[4] = {y4.x, y4.y, y4.z, y4.w};
            unsigned byte = 0;
#pragma unroll
            for (int c = 0; c < 4; ++c) {
                float y = ys[c];
                float dmin = fminf(fabsf(y-bb0), fminf(fabsf(y-bb1), fabsf(y-bb2)));
                if (dmin < TAU_Y) {
                    float n = sNorm[key];
                    const float* kg = keys_blk + (size_t)key*Dn;
                    const float* rr = rot + (size_t)(4*lane + c)*Dn;
                    float acc = 0.f;
                    for (int d = 0; d < Dn; ++d)
                        acc = __fmaf_rn(__fdiv_rn(__ldg(kg + d), n), __ldg(rr + d), acc);
                    y = acc;
                }
                unsigned cc = (unsigned)(y > bb0) + (unsigned)(y > bb1) + (unsigned)(y > bb2);
                byte |= cc << (2*c);
            }
            sCodeB[key*32 + lane] = (unsigned char)byte;
        }
    }
    __syncthreads();

    /* reload union slot with fp32 R (row-major) for phase 2 */
    {
        const float4* g = (const float4*)rot; float4* s = (float4*)uM;
#pragma unroll
        for (int i = tid; i < Dn*Dn/4; i += NTHREADS) s[i] = g[i];
    }
    __syncthreads();

    /* ===== phase 2 (fp32, R12 verbatim): keys_mse chain; residual; r_hat ===== */
    {
        const float* sMf = (const float*)uM;
        u64 axy[16], azw[16];
#pragma unroll
        for (int i = 0; i < 16; ++i) { axy[i] = 0ULL; azw[i] = 0ULL; }
        for (int g = 0; g < 32; ++g) {
            u64 rx[4], rz[4];
#pragma unroll
            for (int dd = 0; dd < 4; ++dd) {
                float4 r = ((const float4*)sMf)[(4*g+dd)*32 + lane];
                rx[dd] = pk2(r.x, r.y); rz[dd] = pk2(r.z, r.w);
            }
#pragma unroll
            for (int h = 0; h < 2; ++h) {
                float xs[8][4];
#pragma unroll
                for (int i = 0; i < 8; ++i) {
                    float4 x = ((const float4*)sTab)[sCodeB[(kb + h*8 + i)*32 + g]];
                    xs[i][0]=x.x; xs[i][1]=x.y; xs[i][2]=x.z; xs[i][3]=x.w;
                }
#pragma unroll
                for (int dd = 0; dd < 4; ++dd)
#pragma unroll
                    for (int i = 0; i < 8; ++i) {
                        u64 xx = dup2(xs[i][dd]);
                        fma2(axy[h*8+i], xx, rx[dd]);
                        fma2(azw[h*8+i], xx, rz[dd]);
                    }
            }
        }
#pragma unroll
        for (int i = 0; i < 16; ++i) {
            int key = kb + i;
            float n = sNorm[key];
            float2 lo = unpk(axy[i]), hi = unpk(azw[i]);
            float4 kg = ((const float4*)(keys_blk + (size_t)key*Dn))[lane];
            float4 r;
            r.x = __fadd_rn(kg.x, -__fmul_rn(lo.x, n));
            r.y = __fadd_rn(kg.y, -__fmul_rn(lo.y, n));
            r.z = __fadd_rn(kg.z, -__fmul_rn(hi.x, n));
            r.w = __fadd_rn(kg.w, -__fmul_rn(hi.y, n));
            float ss = __fmul_rn(r.x, r.x);
            ss = __fmaf_rn(r.y, r.y, ss);
            ss = __fmaf_rn(r.z, r.z, ss);
            ss = __fmaf_rn(r.w, r.w, ss);
            ss = wsum(ss);
            float rn = fmaxf(__fsqrt_rn(ss), 1e-10f);
            if (lane == 0) sRn[key] = rn;
            float4 rh;
            rh.x = __fdiv_rn(r.x, rn);
            rh.y = __fdiv_rn(r.y, rn);
            rh.z = __fdiv_rn(r.z, rn);
            rh.w = __fdiv_rn(r.w, rn);
            ((float4*)(sK + key*Dn))[lane] = rh;   /* y -> r_hat */
        }
    }
    __syncthreads();

    /* reload union slot: S bf16 images */
    {
        const float4* g = (const float4*)g_BS16; float4* s = (float4*)uM;
#pragma unroll
        for (int i = tid; i < (2*Dn*PADB*2)/16; i += NTHREADS) s[i] = g[i];
    }
    __syncthreads();

    /* ===== phase 3 (TENSOR): P = split(r_hat) @ split(S)^T; signs ===== */
    {
        const u16* Bh = (const u16*)uM;
        const u16* Bl = Bh + Dn*PADB;
        const float* rowA = sK + (kb + gid)*Dn;
        const float* rowB = sK + (kb + 8 + gid)*Dn;
        u32 AH[8][4], AL[8][4];
#pragma unroll
        for (int kc = 0; kc < 8; ++kc) {
            int d0 = 16*kc + 2*tig;
            cvt_split(*(const float2*)(rowA + d0),     AH[kc][0], AL[kc][0]);
            cvt_split(*(const float2*)(rowB + d0),     AH[kc][1], AL[kc][1]);
            cvt_split(*(const float2*)(rowA + d0 + 8), AH[kc][2], AL[kc][2]);
            cvt_split(*(const float2*)(rowB + d0 + 8), AH[kc][3], AL[kc][3]);
        }
        __syncwarp();
        u32 mA_A = 0, mB_A = 0, mA_B = 0, mB_B = 0;
#pragma unroll 4
        for (int nt = 0; nt < 16; ++nt) {
            float c0 = 0.f, c1 = 0.f, c2 = 0.f, c3 = 0.f;
            const u16* bh = Bh + (8*nt + gid)*PADB + 2*tig;
            const u16* bl = Bl + (8*nt + gid)*PADB + 2*tig;
#pragma unroll
            for (int kc = 0; kc < 8; ++kc) {
                u32 b0 = *(const u32*)(bh + 16*kc);
                u32 b1 = *(const u32*)(bh + 16*kc + 8);
                u32 d0 = *(const u32*)(bl + 16*kc);
                u32 d1 = *(const u32*)(bl + 16*kc + 8);
                mma16816(c0,c1,c2,c3, AH[kc][0],AH[kc][1],AH[kc][2],AH[kc][3], b0,b1);
                mma16816(c0,c1,c2,c3, AL[kc][0],AL[kc][1],AL[kc][2],AL[kc][3], b0,b1);
                mma16816(c0,c1,c2,c3, AH[kc][0],AH[kc][1],AH[kc][2],AH[kc][3], d0,d1);
            }
            int m0 = 8*nt + 2*tig;
            if (fabsf(c0) < TAU_P) {
                const float* sp = Sm + (size_t)m0*Dn; float acc = 0.f;
                for (int d = 0; d < Dn; ++d) acc = __fmaf_rn(rowA[d], __ldg(sp + d), acc);
                c0 = acc;
            }
            if (fabsf(c1) < TAU_P) {
                const float* sp = Sm + (size_t)(m0+1)*Dn; float acc = 0.f;
                for (int d = 0; d < Dn; ++d) acc = __fmaf_rn(rowA[d], __ldg(sp + d), acc);
                c1 = acc;
            }
            if (fabsf(c2) < TAU_P) {
                const float* sp = Sm + (size_t)m0*Dn; float acc = 0.f;
                for (int d = 0; d < Dn; ++d) acc = __fmaf_rn(rowB[d], __ldg(sp + d), acc);
                c2 = acc;
            }
            if (fabsf(c3) < TAU_P) {
                const float* sp = Sm + (size_t)(m0+1)*Dn; float acc = 0.f;
                for (int d = 0; d < Dn; ++d) acc = __fmaf_rn(rowB[d], __ldg(sp + d), acc);
                c3 = acc;
            }
            u32 g0bit = 1u << (2*nt + (tig >> 1));
            if (c0 >= 0.f) mA_A |= g0bit;
            if (c1 >= 0.f) mB_A |= g0bit;
            if (c2 >= 0.f) mA_B |= g0bit;
            if (c3 >= 0.f) mB_B |= g0bit;
        }
        /* combine g-parity halves across the quad (lane ^ 2) and store */
        mA_A |= __shfl_xor_sync(0xffffffffu, mA_A, 2);
        mB_A |= __shfl_xor_sync(0xffffffffu, mB_A, 2);
        mA_B |= __shfl_xor_sync(0xffffffffu, mA_B, 2);
        mB_B |= __shfl_xor_sync(0xffffffffu, mB_B, 2);
        if ((lane & 2) == 0) {
            int cbase = (lane & 1) * 2;
            sSign[(kb + gid)*4 + cbase]         = mA_A;
            sSign[(kb + gid)*4 + cbase + 1]     = mB_A;
            sSign[(kb + 8 + gid)*4 + cbase]     = mA_B;
            sSign[(kb + 8 + gid)*4 + cbase + 1] = mB_B;
        }
    }
    __syncthreads();

    /* ===== epilogue (R12 verbatim) ===== */
    {
        const float cq = 0.0097915167f;
        const int q0 = 2*w, q1 = 2*w + 1;
        const float* qr0 = sQR + q0*Dn;
        const float* qr1 = sQR + q1*Dn;
        const float* qs0 = sQS + q0*Dn;
        const float* qs1 = sQS + q1*Dn;
        float* og = out + ((size_t)bh*SQn)*SKn + k0;

#pragma unroll
        for (int kc = 0; kc < 4; ++kc) {
            const int key = lane + 32*kc;
            const unsigned char* cK = sCodeB + key*32;
            float e0 = 0.f, e1 = 0.f;
#pragma unroll 4
            for (int g = 0; g < 32; ++g) {
                float4 a0 = ((const float4*)qr0)[g];
                float4 a1 = ((const float4*)qr1)[g];
                float4 yv = ((const float4*)sTab)[cK[g]];
                e0 = __fmaf_rn(a0.x, yv.x, e0); e0 = __fmaf_rn(a0.y, yv.y, e0);
                e0 = __fmaf_rn(a0.z, yv.z, e0); e0 = __fmaf_rn(a0.w, yv.w, e0);
                e1 = __fmaf_rn(a1.x, yv.x, e1); e1 = __fmaf_rn(a1.y, yv.y, e1);
                e1 = __fmaf_rn(a1.z, yv.z, e1); e1 = __fmaf_rn(a1.w, yv.w, e1);
            }
            unsigned w0 = sSign[key*4+0], w1 = sSign[key*4+1],
                     w2 = sSign[key*4+2], w3 = sSign[key*4+3];
            float s0 = 0.f, s1 = 0.f;
#pragma unroll 4
            for (int g = 0; g < 32; ++g) {
                float4 b0 = ((const float4*)qs0)[g];
                float4 b1 = ((const float4*)qs1)[g];
                float f0 = ((w0 >> g) & 1u) ? 1.f : -1.f;
                float f1 = ((w1 >> g) & 1u) ? 1.f : -1.f;
                float f2 = ((w2 >> g) & 1u) ? 1.f : -1.f;
                float f3 = ((w3 >> g) & 1u) ? 1.f : -1.f;
                s0 = __fmaf_rn(f0, b0.x, s0); s0 = __fmaf_rn(f1, b0.y, s0);
                s0 = __fmaf_rn(f2, b0.z, s0); s0 = __fmaf_rn(f3, b0.w, s0);
                s1 = __fmaf_rn(f0, b1.x, s1); s1 = __fmaf_rn(f1, b1.y, s1);
                s1 = __fmaf_rn(f2, b1.z, s1); s1 = __fmaf_rn(f3, b1.w, s1);
            }
            float n = sNorm[key], g2 = cq * sRn[key];
            og[(size_t)q0*SKn + key] = n*e0 + g2*s0;
            og[(size_t)q1*SKn + key] = n*e1 + g2*s1;
        }
    }
}

extern "C" void kernel_launch(void* const* d_in, const int* in_sizes, int n_in,
                              void* d_out, int out_size)
{
    const float* query  = (const float*)d_in[0];
    const float* keys   = (const float*)d_in[1];
    const float* rot    = (const float*)d_in[2];
    const float* S      = (const float*)d_in[3];
    const float* levels = (const float*)d_in[4];
    float* out = (float*)d_out;

    prep1<<<Dn, Dn>>>(rot, S);
    prep_q<<<BHn*SQn, Dn>>>(query);
    turbo_main<<<NBLOCKS, NTHREADS>>>(keys, rot, S, levels, out);
}